// round 2
// baseline (speedup 1.0000x reference)
#include <cuda_runtime.h>
#include <cuda_bf16.h>
#include <math.h>

// ---------------------------------------------------------------------------
// Problem constants
// ---------------------------------------------------------------------------
#define BATCH   2
#define SEQ     2048
#define EMBED   1024
#define HEADS   16
#define HDIM    64
#define HIDDEN  4096
#define MTOT    (BATCH * SEQ)          // 4096 rows
#define LN_EPS  1e-5f

// ---------------------------------------------------------------------------
// Scratch (device globals — allocation-free rule)
// ---------------------------------------------------------------------------
__device__ float g_q   [MTOT * EMBED];
__device__ float g_k   [MTOT * EMBED];
__device__ float g_v   [MTOT * EMBED];
__device__ float g_ao  [MTOT * EMBED];   // attn @ V  (B,S,D)
__device__ float g_tmp [MTOT * EMBED];   // Wo output
__device__ float g_h   [MTOT * EMBED];   // post-LN1
__device__ float g_hid [MTOT * HIDDEN];  // gelu(h@W1+b1)
__device__ float g_mlp [MTOT * EMBED];   // W2 output

// ---------------------------------------------------------------------------
// Generic batched SGEMM: C = act(alpha * A @ B(^T) + bias)
//   A: [M,K] row-major, lda
//   B: TRANSB ? [N,K] : [K,N], ldb
//   C: [M,N] row-major, ldc
// Batch offset for grid z: b = z / Hn, h = z % Hn;  ptr += b*s?b + h*s?h
// Requirements: M % 128 == 0, K % 16 == 0 (holds for every call here).
// N handled with guards (attn@V has N=64).
// ---------------------------------------------------------------------------
#define BM 128
#define BN 128
#define BK 16

__device__ __forceinline__ float gelu_exact(float x) {
    return 0.5f * x * (1.0f + erff(x * 0.70710678118654752f));
}

template <bool TRANSB>
__global__ void __launch_bounds__(256)
sgemm_kernel(int M, int N, int K,
             const float* __restrict__ A, int lda,
             const float* __restrict__ B, int ldb,
             float*       __restrict__ C, int ldc,
             const float* __restrict__ bias,
             float alpha, int act,
             long long sAb, long long sAh,
             long long sBb, long long sBh,
             long long sCb, long long sCh, int Hn)
{
    __shared__ float As[BK][BM];
    __shared__ float Bs[BK][BN];

    const int z  = blockIdx.z;
    const int bb = z / Hn;
    const int hh = z % Hn;
    A += (long long)bb * sAb + (long long)hh * sAh;
    B += (long long)bb * sBb + (long long)hh * sBh;
    C += (long long)bb * sCb + (long long)hh * sCh;

    const int bm  = blockIdx.y * BM;
    const int bn  = blockIdx.x * BN;
    const int tid = threadIdx.x;
    const int tr  = tid >> 4;        // 0..15
    const int tc  = tid & 15;        // 0..15

    // load mapping (128 rows x 16 cols tile = 512 float4, 2 per thread)
    const int aRow0 = tid >> 2;        // 0..63
    const int aCol4 = (tid & 3) * 4;   // 0,4,8,12
    // non-trans B tile (16 x 128) mapping
    const int bRowK = tid >> 5;        // 0..7
    const int bCol4 = (tid & 31) * 4;  // 0..124

    float acc[8][8];
#pragma unroll
    for (int i = 0; i < 8; i++)
#pragma unroll
        for (int j = 0; j < 8; j++) acc[i][j] = 0.f;

    for (int k0 = 0; k0 < K; k0 += BK) {
        // ---- load A tile (always in-bounds: M%128==0, K%16==0) ----
#pragma unroll
        for (int rr = 0; rr < 2; rr++) {
            int row = aRow0 + rr * 64;
            float4 a = *(const float4*)(A + (long long)(bm + row) * lda + k0 + aCol4);
            As[aCol4 + 0][row] = a.x;
            As[aCol4 + 1][row] = a.y;
            As[aCol4 + 2][row] = a.z;
            As[aCol4 + 3][row] = a.w;
        }
        // ---- load B tile ----
        if (TRANSB) {
#pragma unroll
            for (int rr = 0; rr < 2; rr++) {
                int nrow = aRow0 + rr * 64;
                float4 b = make_float4(0.f, 0.f, 0.f, 0.f);
                if (bn + nrow < N)
                    b = *(const float4*)(B + (long long)(bn + nrow) * ldb + k0 + aCol4);
                Bs[aCol4 + 0][nrow] = b.x;
                Bs[aCol4 + 1][nrow] = b.y;
                Bs[aCol4 + 2][nrow] = b.z;
                Bs[aCol4 + 3][nrow] = b.w;
            }
        } else {
#pragma unroll
            for (int rr = 0; rr < 2; rr++) {
                int krow = bRowK + rr * 8;
                const float* src = B + (long long)(k0 + krow) * ldb + bn + bCol4;
                if (bn + bCol4 + 3 < N) {
                    *(float4*)&Bs[krow][bCol4] = *(const float4*)src;
                } else {
#pragma unroll
                    for (int e = 0; e < 4; e++)
                        Bs[krow][bCol4 + e] = (bn + bCol4 + e < N) ? src[e] : 0.f;
                }
            }
        }
        __syncthreads();

        // ---- compute ----
#pragma unroll
        for (int kk = 0; kk < BK; kk++) {
            float a[8], b[8];
            *(float4*)&a[0] = *(const float4*)&As[kk][tr * 4];
            *(float4*)&a[4] = *(const float4*)&As[kk][64 + tr * 4];
            *(float4*)&b[0] = *(const float4*)&Bs[kk][tc * 4];
            *(float4*)&b[4] = *(const float4*)&Bs[kk][64 + tc * 4];
#pragma unroll
            for (int i = 0; i < 8; i++)
#pragma unroll
                for (int j = 0; j < 8; j++)
                    acc[i][j] = fmaf(a[i], b[j], acc[i][j]);
        }
        __syncthreads();
    }

    // ---- epilogue ----
#pragma unroll
    for (int i = 0; i < 8; i++) {
        int row = bm + ((i < 4) ? (tr * 4 + i) : (64 + tr * 4 + i - 4));
#pragma unroll
        for (int j = 0; j < 8; j++) {
            int col = bn + ((j < 4) ? (tc * 4 + j) : (64 + tc * 4 + j - 4));
            if (col < N) {
                float v = acc[i][j] * alpha;
                if (bias) v += bias[col];
                if (act == 1) v = gelu_exact(v);
                C[(long long)row * ldc + col] = v;
            }
        }
    }
}

// ---------------------------------------------------------------------------
// Row softmax, in-place, rows of length SEQ=2048, one block (256 thr) per row
// ---------------------------------------------------------------------------
__global__ void __launch_bounds__(256)
softmax_kernel(float* __restrict__ attn)
{
    const int S = SEQ;
    float* p = attn + (long long)blockIdx.x * S;
    const int tid  = threadIdx.x;
    const int lane = tid & 31;
    const int wid  = tid >> 5;

    float v[8];
    float mx = -1e30f;
#pragma unroll
    for (int i = 0; i < 8; i++) {
        v[i] = p[i * 256 + tid];
        mx = fmaxf(mx, v[i]);
    }
#pragma unroll
    for (int o = 16; o; o >>= 1) mx = fmaxf(mx, __shfl_xor_sync(0xffffffffu, mx, o));

    __shared__ float red[8];
    if (lane == 0) red[wid] = mx;
    __syncthreads();
    float m = red[0];
#pragma unroll
    for (int i = 1; i < 8; i++) m = fmaxf(m, red[i]);

    float sum = 0.f;
#pragma unroll
    for (int i = 0; i < 8; i++) {
        v[i] = __expf(v[i] - m);
        sum += v[i];
    }
#pragma unroll
    for (int o = 16; o; o >>= 1) sum += __shfl_xor_sync(0xffffffffu, sum, o);
    __syncthreads();
    if (lane == 0) red[wid] = sum;
    __syncthreads();
    float tot = 0.f;
#pragma unroll
    for (int i = 0; i < 8; i++) tot += red[i];
    float inv = 1.0f / tot;
#pragma unroll
    for (int i = 0; i < 8; i++) p[i * 256 + tid] = v[i] * inv;
}

// ---------------------------------------------------------------------------
// out = LayerNorm(a + b) * gamma + beta ; rows of EMBED=1024, 256 thr/row
// ---------------------------------------------------------------------------
__global__ void __launch_bounds__(256)
add_ln_kernel(const float* __restrict__ a, const float* __restrict__ b,
              const float* __restrict__ gamma, const float* __restrict__ beta,
              float* __restrict__ out)
{
    const int D = EMBED;
    const long long base = (long long)blockIdx.x * D;
    const int tid  = threadIdx.x;
    const int lane = tid & 31;
    const int wid  = tid >> 5;

    float v[4];
    float s1 = 0.f, s2 = 0.f;
#pragma unroll
    for (int i = 0; i < 4; i++) {
        int col = i * 256 + tid;
        float x = a[base + col] + b[base + col];
        v[i] = x;
        s1 += x;
        s2 += x * x;
    }
#pragma unroll
    for (int o = 16; o; o >>= 1) {
        s1 += __shfl_xor_sync(0xffffffffu, s1, o);
        s2 += __shfl_xor_sync(0xffffffffu, s2, o);
    }
    __shared__ float r1[8], r2[8];
    if (lane == 0) { r1[wid] = s1; r2[wid] = s2; }
    __syncthreads();
    float t1 = 0.f, t2 = 0.f;
#pragma unroll
    for (int i = 0; i < 8; i++) { t1 += r1[i]; t2 += r2[i]; }
    float mu  = t1 * (1.0f / D);
    float var = t2 * (1.0f / D) - mu * mu;
    float inv = rsqrtf(var + LN_EPS);
#pragma unroll
    for (int i = 0; i < 4; i++) {
        int col = i * 256 + tid;
        out[base + col] = (v[i] - mu) * inv * gamma[col] + beta[col];
    }
}

// ---------------------------------------------------------------------------
// Host launcher
// ---------------------------------------------------------------------------
extern "C" void kernel_launch(void* const* d_in, const int* in_sizes, int n_in,
                              void* d_out, int out_size)
{
    const float* x  = (const float*)d_in[0];
    const float* Wq = (const float*)d_in[1];
    const float* bq = (const float*)d_in[2];
    const float* Wk = (const float*)d_in[3];
    const float* bk = (const float*)d_in[4];
    const float* Wv = (const float*)d_in[5];
    const float* bv = (const float*)d_in[6];
    const float* Wo = (const float*)d_in[7];
    const float* bo = (const float*)d_in[8];
    const float* W1 = (const float*)d_in[9];
    const float* b1 = (const float*)d_in[10];
    const float* W2 = (const float*)d_in[11];
    const float* b2 = (const float*)d_in[12];
    const float* gamma = (const float*)d_in[13];
    const float* beta  = (const float*)d_in[14];

    float* out  = (float*)d_out;                       // [B,S,D]
    float* attn = out + (long long)MTOT * EMBED;       // [B,H,S,S]

    float *q, *k, *v, *ao, *tmp, *h, *hid, *mlp;
    cudaGetSymbolAddress((void**)&q,   g_q);
    cudaGetSymbolAddress((void**)&k,   g_k);
    cudaGetSymbolAddress((void**)&v,   g_v);
    cudaGetSymbolAddress((void**)&ao,  g_ao);
    cudaGetSymbolAddress((void**)&tmp, g_tmp);
    cudaGetSymbolAddress((void**)&h,   g_h);
    cudaGetSymbolAddress((void**)&hid, g_hid);
    cudaGetSymbolAddress((void**)&mlp, g_mlp);

    const dim3 blk(256);
    const long long SD  = (long long)SEQ * EMBED;       // batch stride of x/q/k/v
    const long long SS  = (long long)SEQ * SEQ;         // per-head attn stride

    // --- QKV projections ---
    sgemm_kernel<false><<<dim3(EMBED / BN, MTOT / BM, 1), blk>>>(
        MTOT, EMBED, EMBED, x, EMBED, Wq, EMBED, q, EMBED, bq, 1.f, 0,
        0, 0, 0, 0, 0, 0, 1);
    sgemm_kernel<false><<<dim3(EMBED / BN, MTOT / BM, 1), blk>>>(
        MTOT, EMBED, EMBED, x, EMBED, Wk, EMBED, k, EMBED, bk, 1.f, 0,
        0, 0, 0, 0, 0, 0, 1);
    sgemm_kernel<false><<<dim3(EMBED / BN, MTOT / BM, 1), blk>>>(
        MTOT, EMBED, EMBED, x, EMBED, Wv, EMBED, v, EMBED, bv, 1.f, 0,
        0, 0, 0, 0, 0, 0, 1);

    // --- energy = (Q @ K^T) / sqrt(d)  -> written straight into attn slice ---
    sgemm_kernel<true><<<dim3(SEQ / BN, SEQ / BM, BATCH * HEADS), blk>>>(
        SEQ, SEQ, HDIM, q, EMBED, k, EMBED, attn, SEQ, nullptr, 0.125f, 0,
        SD, HDIM, SD, HDIM, (long long)HEADS * SS, SS, HEADS);

    // --- softmax rows (in place) ---
    softmax_kernel<<<BATCH * HEADS * SEQ, 256>>>(attn);

    // --- attn @ V ---
    sgemm_kernel<false><<<dim3(1, SEQ / BM, BATCH * HEADS), blk>>>(
        SEQ, HDIM, SEQ, attn, SEQ, v, EMBED, ao, EMBED, nullptr, 1.f, 0,
        (long long)HEADS * SS, SS, SD, HDIM, SD, HDIM, HEADS);

    // --- output projection ---
    sgemm_kernel<false><<<dim3(EMBED / BN, MTOT / BM, 1), blk>>>(
        MTOT, EMBED, EMBED, ao, EMBED, Wo, EMBED, tmp, EMBED, bo, 1.f, 0,
        0, 0, 0, 0, 0, 0, 1);

    // --- h = LN(x + attn_proj) ---
    add_ln_kernel<<<MTOT, 256>>>(x, tmp, gamma, beta, h);

    // --- MLP: gelu(h @ W1 + b1) ---
    sgemm_kernel<false><<<dim3(HIDDEN / BN, MTOT / BM, 1), blk>>>(
        MTOT, HIDDEN, EMBED, h, EMBED, W1, HIDDEN, hid, HIDDEN, b1, 1.f, 1,
        0, 0, 0, 0, 0, 0, 1);

    // --- mlp = hid @ W2 + b2 ---
    sgemm_kernel<false><<<dim3(EMBED / BN, MTOT / BM, 1), blk>>>(
        MTOT, EMBED, HIDDEN, hid, HIDDEN, W2, EMBED, mlp, EMBED, b2, 1.f, 0,
        0, 0, 0, 0, 0, 0, 1);

    // --- out = LN(mlp + h) ---
    add_ln_kernel<<<MTOT, 256>>>(mlp, h, gamma, beta, out);
}